// round 2
// baseline (speedup 1.0000x reference)
#include <cuda_runtime.h>
#include <math.h>

// Shapes (fixed)
#define BN   2048
#define NN   256
#define DIN  128
#define DE   64
#define HH   128
#define MD   1664

typedef unsigned long long ull;

// Scratch
__device__ float  g_hi[BN * DIN];
__device__ float  g_hj[BN * DIN];
__device__ float  g_m[(size_t)BN * MD];
__device__ float2 g_Wih2[DIN * 3 * HH];   // [c][row] duplicated (w,w)
__device__ float2 g_Whh2[DIN * 3 * HH];

// ---- f32x2 packed helpers -------------------------------------------------
__device__ __forceinline__ ull ffma2(ull a, ull b, ull c) {
    ull d;
    asm("fma.rn.f32x2 %0, %1, %2, %3;" : "=l"(d) : "l"(a), "l"(b), "l"(c));
    return d;
}
__device__ __forceinline__ ull pack1(float w) {
    ull d; asm("mov.b64 %0, {%1,%2};" : "=l"(d) : "f"(w), "f"(w)); return d;
}
__device__ __forceinline__ void unpack2(ull v, float& x, float& y) {
    asm("mov.b64 {%0,%1}, %2;" : "=f"(x), "=f"(y) : "l"(v));
}

// ---------------------------------------------------------------------------
// K0: build duplicated-packed transposed GRU weights
// ---------------------------------------------------------------------------
__global__ void k0_prep(const float* __restrict__ Wih,
                        const float* __restrict__ Whh) {
    int idx = blockIdx.x * 128 + threadIdx.x;  // 384 blocks
    if (idx < 384 * 128) {
        int r = idx >> 7, c = idx & 127;
        float a = Wih[idx], b = Whh[idx];
        g_Wih2[c * 384 + r] = make_float2(a, a);
        g_Whh2[c * 384 + r] = make_float2(b, b);
    }
}

// ---------------------------------------------------------------------------
// K1: hi/hj projections + copy input into g_m[:,0:128]
// ---------------------------------------------------------------------------
__global__ void __launch_bounds__(128) k1_hij(const float* __restrict__ input,
                                              const float* __restrict__ preW) {
    __shared__ float As[16 * 128];
    int t = threadIdx.x;
    int n0 = blockIdx.x * 16;

    for (int s = t; s < 16 * 128; s += 128) {
        float v = input[(size_t)n0 * 128 + s];
        As[s] = v;
        g_m[(size_t)(n0 + (s >> 7)) * MD + (s & 127)] = v;
    }
    __syncthreads();

    float hi[16], hj[16];
#pragma unroll
    for (int r = 0; r < 16; r++) { hi[r] = 0.f; hj[r] = 0.f; }

    for (int e = 0; e < 128; e += 4) {
        float wi0 = preW[(e + 0) * 128 + t];
        float wi1 = preW[(e + 1) * 128 + t];
        float wi2 = preW[(e + 2) * 128 + t];
        float wi3 = preW[(e + 3) * 128 + t];
        float wj0 = preW[(128 + e + 0) * 128 + t];
        float wj1 = preW[(128 + e + 1) * 128 + t];
        float wj2 = preW[(128 + e + 2) * 128 + t];
        float wj3 = preW[(128 + e + 3) * 128 + t];
#pragma unroll
        for (int r = 0; r < 16; r++) {
            const float4 a = *(const float4*)&As[r * 128 + e];
            hi[r] += a.x * wi0 + a.y * wi1 + a.z * wi2 + a.w * wi3;
            hj[r] += a.x * wj0 + a.y * wj1 + a.z * wj2 + a.w * wj3;
        }
    }
#pragma unroll
    for (int r = 0; r < 16; r++) {
        g_hi[(size_t)(n0 + r) * 128 + t] = hi[r];
        g_hj[(size_t)(n0 + r) * 128 + t] = hj[r];
    }
}

// ---------------------------------------------------------------------------
// K2: per-node sparse aggregation (unchanged — ~10us, revisit if dominant)
// ---------------------------------------------------------------------------
__global__ void __launch_bounds__(128) k2_agg(const float* __restrict__ adj,
                                              const float* __restrict__ adjf,
                                              const float* __restrict__ preW,
                                              const float* __restrict__ preb) {
    __shared__ float WeS[DE * 128];
    __shared__ float efT[DE * 4];
    __shared__ int   nbr[NN];
    __shared__ int   cnt;

    int t = threadIdx.x;
    int node = blockIdx.x;
    int nbase = (node >> 8) << 8;

    for (int s = t; s < DE * 128; s += 128) WeS[s] = preW[256 * 128 + s];
    if (t == 0) cnt = 0;
    __syncthreads();

    const float* arow = adj + (size_t)node * NN;
    for (int j = t; j < NN; j += 128)
        if (arow[j] > 0.0f) { int p = atomicAdd(&cnt, 1); nbr[p] = j; }
    __syncthreads();

    int deg = cnt;
    float base = g_hi[(size_t)node * 128 + t] + preb[t];
    float s1 = 0.f, s2 = 0.f, mx = -1e30f, mn = 1e30f;
    const float* efb = adjf + (size_t)node * NN * DE;

    for (int p0 = 0; p0 < deg; p0 += 4) {
        int nb = deg - p0; if (nb > 4) nb = 4;
        __syncthreads();
        for (int s = t; s < DE * 4; s += 128) {
            int u = s & 3, e = s >> 2;
            efT[s] = (u < nb) ? efb[(size_t)nbr[p0 + u] * DE + e] : 0.0f;
        }
        __syncthreads();

        float hjv[4];
#pragma unroll
        for (int u = 0; u < 4; u++) {
            int uu = (u < nb) ? u : 0;
            hjv[u] = g_hj[(size_t)(nbase + nbr[p0 + uu]) * 128 + t];
        }

        float e0 = 0.f, e1 = 0.f, e2 = 0.f, e3 = 0.f;
#pragma unroll
        for (int e = 0; e < DE; e++) {
            float w = WeS[e * 128 + t];
            const float4 v = *(const float4*)&efT[e * 4];
            e0 += v.x * w; e1 += v.y * w; e2 += v.z * w; e3 += v.w * w;
        }
        float ev[4] = {e0, e1, e2, e3};
#pragma unroll
        for (int u = 0; u < 4; u++) {
            if (p0 + u < deg) {
                float tv = base + hjv[u] + ev[u];
                s1 += tv; s2 += tv * tv;
                mx = fmaxf(mx, tv); mn = fminf(mn, tv);
            }
        }
    }

    float degf = (float)deg;
    float degc = fmaxf(degf, 1e-5f);
    float mean = s1 / degc;
    float var = s2 / degc - mean * mean;
    if (var < 0.f) var = 0.f;
    float sd = sqrtf(var + 1e-5f);
    float mxo = (deg > 0) ? mx : 0.f;
    float mno = (deg > 0) ? mn : 0.f;
    float slog = logf(degf + 1.0f) / 3.3f;
    float inv = 1.0f / (slog + 1e-5f);

    float* mrow = g_m + (size_t)node * MD;
    mrow[ 128 + t] = mean;        mrow[ 256 + t] = mxo;
    mrow[ 384 + t] = mno;         mrow[ 512 + t] = sd;
    mrow[ 640 + t] = mean * slog; mrow[ 768 + t] = mxo * slog;
    mrow[ 896 + t] = mno * slog;  mrow[1024 + t] = sd * slog;
    mrow[1152 + t] = mean * inv;  mrow[1280 + t] = mxo * inv;
    mrow[1408 + t] = mno * inv;   mrow[1536 + t] = sd * inv;
}

// ---------------------------------------------------------------------------
// K3 v2: fused tail, f32x2 packed, smem-staged weights, 512 threads.
// Block: 16 rows x 128 cols. Thread: col t = tid&127, quad q = tid>>7 owns
// rows q*4..q*4+3 as two f32x2 pairs.
// ---------------------------------------------------------------------------
#define KT   32          // post k-tile
#define KTG  8           // GRU k-tile
#define NT   52          // MD / KT
#define PAD  20          // transposed-tile row stride (16B-aligned pairs, low conflicts)

// smem layout (bytes):
//   [0, 49152)          WBUF: post Ws2 (4096 float2 = 32KB) / GRU WihS2+WhhS2 (2x24KB)
//   [49152, +2560)      AsT  : KT x PAD floats
//   [51712, +10240)     YsT  : 128 x PAD floats (y1 transposed)
//   [61952, +10240)     XsT  : 128 x PAD floats (y2 transposed)
//   [72192, +10240)     HsT  : 128 x PAD floats (hidden transposed)
#define SMEM_K3 82432

__global__ void __launch_bounds__(512, 1) k3_tail(
        const float* __restrict__ postW, const float* __restrict__ postb,
        const float* __restrict__ mixW,  const float* __restrict__ mixb,
        const float* __restrict__ hidden, float* __restrict__ out) {
    extern __shared__ char smem[];
    float2* Ws2   = (float2*)smem;
    float2* WihS2 = (float2*)smem;                    // 3072 float2
    float2* WhhS2 = ((float2*)smem) + 3072;
    float*  AsT   = (float*)(smem + 49152);
    float*  YsT   = AsT + KT * PAD;
    float*  XsT   = YsT + 128 * PAD;
    float*  HsT   = XsT + 128 * PAD;

    const int tid = threadIdx.x;
    const int t   = tid & 127;
    const int q   = tid >> 7;
    const int r0  = q * 4;
    const int n0  = blockIdx.x * 16;

    // ---- stage hidden transposed (HsT[c*PAD + r]) ----
    {
#pragma unroll
        for (int j = 0; j < 4; j++) {
            int idx = tid + j * 512;           // 2048 elements
            int r = idx >> 7, c = idx & 127;
            HsT[c * PAD + r] = hidden[(size_t)(n0 + r) * 128 + c];
        }
    }

    // ---- phase 1: y1 = m_cat @ post_W  (register-relay tiled) ----
    const float4* pw4 = (const float4*)postW;
    float4 wst[2];
    float  ast;
    {
#pragma unroll
        for (int i = 0; i < 2; i++) wst[i] = pw4[tid + i * 512];
        ast = g_m[(size_t)(n0 + (tid >> 5)) * MD + (tid & 31)];
    }

    ull acc01 = 0ull, acc23 = 0ull;
    for (int tile = 0; tile < NT; tile++) {
        if (tile > 0) __syncthreads();
#pragma unroll
        for (int i = 0; i < 2; i++) {
            int fl = tid + i * 512;
            float4 w = wst[i];
            float4* dst = (float4*)&Ws2[fl * 4];
            dst[0] = make_float4(w.x, w.x, w.y, w.y);
            dst[1] = make_float4(w.z, w.z, w.w, w.w);
        }
        AsT[(tid & 31) * PAD + (tid >> 5)] = ast;
        __syncthreads();
        if (tile + 1 < NT) {
#pragma unroll
            for (int i = 0; i < 2; i++) wst[i] = pw4[(tile + 1) * 1024 + tid + i * 512];
            ast = g_m[(size_t)(n0 + (tid >> 5)) * MD + (tile + 1) * KT + (tid & 31)];
        }
#pragma unroll
        for (int kk = 0; kk < KT; kk++) {
            ull ww = *(const ull*)&Ws2[kk * 128 + t];
            longlong2 av = *(const longlong2*)&AsT[kk * PAD + r0];
            acc01 = ffma2((ull)av.x, ww, acc01);
            acc23 = ffma2((ull)av.y, ww, acc23);
        }
    }
    __syncthreads();

    // epilogue: + postb, store transposed to YsT
    {
        float pb = postb[t];
        float y0, y1v, y2, y3;
        unpack2(acc01, y0, y1v); unpack2(acc23, y2, y3);
        *(float2*)&YsT[t * PAD + r0]     = make_float2(y0 + pb, y1v + pb);
        *(float2*)&YsT[t * PAD + r0 + 2] = make_float2(y2 + pb, y3 + pb);
    }
    __syncthreads();

    // ---- prefetch GRU tile 0 into regs (hides behind mix) ----
    const float4* wih4 = (const float4*)g_Wih2;
    const float4* whh4 = (const float4*)g_Whh2;
    float4 gih[3], ghh[3];
#pragma unroll
    for (int i = 0; i < 3; i++) {
        gih[i] = wih4[tid + i * 512];
        ghh[i] = whh4[tid + i * 512];
    }

    // ---- phase 2: y2 = leaky(y1 @ mix_W + mix_b), store transposed XsT ----
    {
        ull m01 = 0ull, m23 = 0ull;
#pragma unroll 4
        for (int k = 0; k < 128; k++) {
            ull ww = pack1(mixW[k * 128 + t]);
            longlong2 yv = *(const longlong2*)&YsT[k * PAD + r0];
            m01 = ffma2((ull)yv.x, ww, m01);
            m23 = ffma2((ull)yv.y, ww, m23);
        }
        float mb = mixb[t];
        float y0, y1v, y2, y3;
        unpack2(m01, y0, y1v); unpack2(m23, y2, y3);
        y0 += mb; y1v += mb; y2 += mb; y3 += mb;
        y0 = (y0 > 0.f) ? y0 : 0.01f * y0;
        y1v = (y1v > 0.f) ? y1v : 0.01f * y1v;
        y2 = (y2 > 0.f) ? y2 : 0.01f * y2;
        y3 = (y3 > 0.f) ? y3 : 0.01f * y3;
        *(float2*)&XsT[t * PAD + r0]     = make_float2(y0, y1v);
        *(float2*)&XsT[t * PAD + r0 + 2] = make_float2(y2, y3);
    }

    // ---- phase 3: GRU (tiled over k, register-relay weights) ----
    ull R01 = 0, R23 = 0, Z01 = 0, Z23 = 0, Gi01 = 0, Gi23 = 0, Gh01 = 0, Gh23 = 0;
    for (int g = 0; g < 16; g++) {
        __syncthreads();   // XsT writes done (g==0) / WBUF readers done (g>0)
        {
            float4* di = (float4*)WihS2;
            float4* dh = (float4*)WhhS2;
#pragma unroll
            for (int i = 0; i < 3; i++) {
                di[tid + i * 512] = gih[i];
                dh[tid + i * 512] = ghh[i];
            }
        }
        __syncthreads();
        if (g + 1 < 16) {
#pragma unroll
            for (int i = 0; i < 3; i++) {
                gih[i] = wih4[(g + 1) * 1536 + tid + i * 512];
                ghh[i] = whh4[(g + 1) * 1536 + tid + i * 512];
            }
        }
#pragma unroll
        for (int kk = 0; kk < KTG; kk++) {
            int k = g * KTG + kk;
            longlong2 xv = *(const longlong2*)&XsT[k * PAD + r0];
            longlong2 hv = *(const longlong2*)&HsT[k * PAD + r0];
            ull wir = *(const ull*)&WihS2[kk * 384 + t];
            ull wiz = *(const ull*)&WihS2[kk * 384 + 128 + t];
            ull win = *(const ull*)&WihS2[kk * 384 + 256 + t];
            ull whr = *(const ull*)&WhhS2[kk * 384 + t];
            ull whz = *(const ull*)&WhhS2[kk * 384 + 128 + t];
            ull whn = *(const ull*)&WhhS2[kk * 384 + 256 + t];
            R01  = ffma2((ull)xv.x, wir, R01);  R01  = ffma2((ull)hv.x, whr, R01);
            R23  = ffma2((ull)xv.y, wir, R23);  R23  = ffma2((ull)hv.y, whr, R23);
            Z01  = ffma2((ull)xv.x, wiz, Z01);  Z01  = ffma2((ull)hv.x, whz, Z01);
            Z23  = ffma2((ull)xv.y, wiz, Z23);  Z23  = ffma2((ull)hv.y, whz, Z23);
            Gi01 = ffma2((ull)xv.x, win, Gi01);
            Gi23 = ffma2((ull)xv.y, win, Gi23);
            Gh01 = ffma2((ull)hv.x, whn, Gh01);
            Gh23 = ffma2((ull)hv.y, whn, Gh23);
        }
    }

    // ---- GRU epilogue ----
    {
        float R[4], Z[4], Gi[4], Gh[4];
        unpack2(R01, R[0], R[1]);   unpack2(R23, R[2], R[3]);
        unpack2(Z01, Z[0], Z[1]);   unpack2(Z23, Z[2], Z[3]);
        unpack2(Gi01, Gi[0], Gi[1]); unpack2(Gi23, Gi[2], Gi[3]);
        unpack2(Gh01, Gh[0], Gh[1]); unpack2(Gh23, Gh[2], Gh[3]);
        float4 hv = *(const float4*)&HsT[t * PAD + r0];
        float hh[4] = {hv.x, hv.y, hv.z, hv.w};
#pragma unroll
        for (int j = 0; j < 4; j++) {
            float r = 1.0f / (1.0f + expf(-R[j]));
            float z = 1.0f / (1.0f + expf(-Z[j]));
            float n = tanhf(Gi[j] + r * Gh[j]);
            out[(size_t)(n0 + r0 + j) * 128 + t] = (1.0f - z) * n + z * hh[j];
        }
    }
}

// ---------------------------------------------------------------------------
extern "C" void kernel_launch(void* const* d_in, const int* in_sizes, int n_in,
                              void* d_out, int out_size) {
    const float* input  = (const float*)d_in[0];
    const float* adj    = (const float*)d_in[1];
    const float* adjf   = (const float*)d_in[2];
    const float* hidden = (const float*)d_in[3];
    const float* preW   = (const float*)d_in[4];
    const float* preb   = (const float*)d_in[5];
    const float* postW  = (const float*)d_in[6];
    const float* postb  = (const float*)d_in[7];
    const float* mixW   = (const float*)d_in[8];
    const float* mixb   = (const float*)d_in[9];
    const float* Wih    = (const float*)d_in[10];
    const float* Whh    = (const float*)d_in[11];
    float* out = (float*)d_out;

    cudaFuncSetAttribute(k3_tail, cudaFuncAttributeMaxDynamicSharedMemorySize, SMEM_K3);

    k0_prep<<<384, 128>>>(Wih, Whh);
    k1_hij<<<128, 128>>>(input, preW);
    k2_agg<<<BN, 128>>>(adj, adjf, preW, preb);
    k3_tail<<<128, 512, SMEM_K3>>>(postW, postb, mixW, mixb, hidden, out);
}